// round 8
// baseline (speedup 1.0000x reference)
#include <cuda_runtime.h>
#include <math.h>
#include <stdint.h>

#define Bn 256
#define Tn 128
#define Fn 1024
#define Hn 512
#define IN1 1152
#define KSP 8          // k1 K-splits

__device__ float g_cp[KSP][Bn * Tn];  // k1 partials (D[t,b] slices)
__device__ float g_e[Bn * Fn];        // logits

__device__ __forceinline__ float tanh_fast(float x) {
    float y; asm("tanh.approx.f32 %0, %1;" : "=f"(y) : "f"(x)); return y;
}
__device__ __forceinline__ uint32_t pack_h2(float hi, float lo) {
    uint32_t d;
    asm("cvt.rn.f16x2.f32 %0, %1, %2;" : "=r"(d) : "f"(hi), "f"(lo));
    return d;
}
__device__ __forceinline__ uint32_t smem_u32(const void* p) {
    uint32_t a;
    asm("{ .reg .u64 t; cvta.to.shared.u64 t, %1; cvt.u32.u64 %0, t; }" : "=r"(a) : "l"(p));
    return a;
}
__device__ __forceinline__ void mma_f16(float* d, const uint4& a, const uint2& b) {
    asm volatile(
        "mma.sync.aligned.m16n8k16.row.col.f32.f16.f16.f32 "
        "{%0,%1,%2,%3}, {%4,%5,%6,%7}, {%8,%9}, {%0,%1,%2,%3};"
        : "+f"(d[0]), "+f"(d[1]), "+f"(d[2]), "+f"(d[3])
        : "r"(a.x), "r"(a.y), "r"(a.z), "r"(a.w), "r"(b.x), "r"(b.y));
}
#define CP_ASYNC4(dst, src) \
    asm volatile("cp.async.ca.shared.global [%0], [%1], 4;" :: "r"(dst), "l"(src) : "memory")
#define CP_COMMIT()  asm volatile("cp.async.commit_group;" ::: "memory")
#define CP_WAIT(n)   asm volatile("cp.async.wait_group %0;" :: "n"(n) : "memory")

// ---------------------------------------------------------------------------
// k1: c partials via fp16 mma. grid (KSP=8, 2). CTA: D[t=128, b=128] for one
// K=128 slice of hs. A = W1[:,128+ksl*128 ..], B = hs (contiguous in k).
// Dynamic smem (u32): A frags [8][8][128] | B frags [16][8][64] = 64KB.
// ---------------------------------------------------------------------------
__global__ __launch_bounds__(256) void k1_mma(
    const float* __restrict__ h, const float* __restrict__ s,
    const float* __restrict__ W1, const float* __restrict__ b1) {
    extern __shared__ uint32_t dynA[];            // A at 0, B at 8192
    int tid = threadIdx.x;
    int w = tid >> 5, lane = tid & 31;
    int wm = w >> 2, wn = w & 3;
    int g = lane >> 2, tq = lane & 3;
    int ksl = blockIdx.x;          // K slice (0..7): j = ksl*128 + kk
    int b0  = blockIdx.y * 128;    // batch tile

    // ---- stage A: warp w -> mt = w (t rows w*16+g, +8) ----
    {
        const float* r0 = W1 + (size_t)(w * 16 + g) * IN1 + Tn + ksl * 128;
        const float* r8 = r0 + 8 * IN1;
        #pragma unroll
        for (int ks = 0; ks < 8; ks++) {
            int c0 = ks * 16 + 2 * tq;
            float2 p00 = *(const float2*)(r0 + c0);
            float2 p10 = *(const float2*)(r8 + c0);
            float2 p01 = *(const float2*)(r0 + c0 + 8);
            float2 p11 = *(const float2*)(r8 + c0 + 8);
            uint4 v;
            v.x = pack_h2(p00.y, p00.x);
            v.y = pack_h2(p10.y, p10.x);
            v.z = pack_h2(p01.y, p01.x);
            v.w = pack_h2(p11.y, p11.x);
            *(uint4*)&dynA[(w * 8 + ks) * 128 + lane * 4] = v;
        }
    }
    // ---- stage B: warp w -> nt = 2w, 2w+1 ; b = b0 + nt*8 + g ----
    {
        const float* base = (ksl < 4) ? h : s;
        int joff = (ksl < 4) ? ksl * 128 : (ksl - 4) * 128;
        #pragma unroll
        for (int jj = 0; jj < 2; jj++) {
            int nt = w * 2 + jj;
            const float* row = base + (size_t)(b0 + nt * 8 + g) * Hn + joff;
            #pragma unroll
            for (int ks = 0; ks < 8; ks++) {
                int k0 = ks * 16 + 2 * tq;
                float2 p0 = *(const float2*)(row + k0);
                float2 p1 = *(const float2*)(row + k0 + 8);
                uint2 bv;
                bv.x = pack_h2(p0.y, p0.x);
                bv.y = pack_h2(p1.y, p1.x);
                *(uint2*)&dynA[8192 + (nt * 8 + ks) * 64 + lane * 2] = bv;
            }
        }
    }
    __syncthreads();

    float acc[4][4][4];
    #pragma unroll
    for (int i = 0; i < 4; i++)
        #pragma unroll
        for (int j = 0; j < 4; j++)
            #pragma unroll
            for (int r = 0; r < 4; r++) acc[i][j][r] = 0.f;

    #pragma unroll
    for (int ks = 0; ks < 8; ks++) {
        uint4 a[4];
        uint2 bf[4];
        #pragma unroll
        for (int i = 0; i < 4; i++)
            a[i] = *(const uint4*)&dynA[((wm * 4 + i) * 8 + ks) * 128 + lane * 4];
        #pragma unroll
        for (int j = 0; j < 4; j++)
            bf[j] = *(const uint2*)&dynA[8192 + ((wn * 4 + j) * 8 + ks) * 64 + lane * 2];
        #pragma unroll
        for (int i = 0; i < 4; i++)
            #pragma unroll
            for (int j = 0; j < 4; j++)
                mma_f16(acc[i][j], a[i], bf[j]);
    }

    // ---- store partials: D[t, b] -> g_cp[ksl][b*Tn + t]  (+ b1 on slice 0) ----
    #pragma unroll
    for (int i = 0; i < 4; i++) {
        int t0 = (wm * 4 + i) * 16 + g;
        float bias0 = (ksl == 0) ? __ldg(&b1[t0])     : 0.f;
        float bias1 = (ksl == 0) ? __ldg(&b1[t0 + 8]) : 0.f;
        #pragma unroll
        for (int j = 0; j < 4; j++) {
            int bc = b0 + (wn * 4 + j) * 8 + 2 * tq;
            g_cp[ksl][(bc)     * Tn + t0]     = acc[i][j][0] + bias0;
            g_cp[ksl][(bc + 1) * Tn + t0]     = acc[i][j][1] + bias0;
            g_cp[ksl][(bc)     * Tn + t0 + 8] = acc[i][j][2] + bias1;
            g_cp[ksl][(bc + 1) * Tn + t0 + 8] = acc[i][j][3] + bias1;
        }
    }
}

// ---------------------------------------------------------------------------
// k2: fp16 mma, B loaded via cp.async (raw fp32, cvt on fragment load),
// A staged as fp16 fragments while B is in flight. Two K-halves (wait 1 / 0).
// Dynamic smem: A frags 8192 u32 (32KB) | B raw 16384 f32 (64KB) = 96KB.
// ---------------------------------------------------------------------------
__global__ __launch_bounds__(256, 2) void k2_main(
    const float* __restrict__ x, const float* __restrict__ W1,
    const float* __restrict__ W2, const float* __restrict__ b2) {
    extern __shared__ uint32_t dyn[];   // A frags at 0; B raw f32 at dyn+8192
    __shared__ float c_s[Tn], w2_s[Tn];
    __shared__ float red2[2][128];

    int tid = threadIdx.x;
    int w = tid >> 5, lane = tid & 31;
    int wm = w >> 2, wn = w & 3;
    int g = lane >> 2, tq = lane & 3;
    int b  = blockIdx.y;
    int f0 = blockIdx.x * 128;

    uint32_t smbase = smem_u32(dyn);
    float* Braw = (float*)(dyn + 8192);

    // ---- issue ALL B cp.asyncs first (2 commit groups: ks 0-3, ks 4-7) ----
    {
        const float* xb = x + (size_t)b * Tn * Fn + f0;
        #pragma unroll
        for (int half = 0; half < 2; half++) {
            #pragma unroll
            for (int jj = 0; jj < 2; jj++) {
                int nt = w * 2 + jj;
                const float* col = xb + nt * 8 + g;
                #pragma unroll
                for (int kss = 0; kss < 4; kss++) {
                    int ks = half * 4 + kss;
                    int k0 = ks * 16 + 2 * tq;
                    uint32_t d0 = smbase + (8192 + (nt * 8 + ks) * 128 + lane * 4) * 4;
                    CP_ASYNC4(d0,      col + (size_t)k0 * Fn);
                    CP_ASYNC4(d0 + 4,  col + (size_t)(k0 + 1) * Fn);
                    CP_ASYNC4(d0 + 8,  col + (size_t)(k0 + 8) * Fn);
                    CP_ASYNC4(d0 + 12, col + (size_t)(k0 + 9) * Fn);
                }
            }
            CP_COMMIT();
        }
    }

    // ---- stage A fragments (fp16) while B flies ----
    {
        const float* r0 = W1 + (size_t)(w * 16 + g) * IN1;
        const float* r8 = r0 + 8 * IN1;
        #pragma unroll
        for (int ks = 0; ks < 8; ks++) {
            int c0 = ks * 16 + 2 * tq;
            float2 p00 = *(const float2*)(r0 + c0);
            float2 p10 = *(const float2*)(r8 + c0);
            float2 p01 = *(const float2*)(r0 + c0 + 8);
            float2 p11 = *(const float2*)(r8 + c0 + 8);
            uint4 v;
            v.x = pack_h2(p00.y, p00.x);
            v.y = pack_h2(p10.y, p10.x);
            v.z = pack_h2(p01.y, p01.x);
            v.w = pack_h2(p11.y, p11.x);
            *(uint4*)&dyn[(w * 8 + ks) * 128 + lane * 4] = v;
        }
    }

    if (tid < Tn) {
        float c = 0.f;
        #pragma unroll
        for (int k = 0; k < KSP; k++) c += g_cp[k][b * Tn + tid];
        c_s[tid]  = c;
        w2_s[tid] = __ldg(&W2[tid]);
    }

    float acc[4][4][4];
    #pragma unroll
    for (int i = 0; i < 4; i++)
        #pragma unroll
        for (int j = 0; j < 4; j++)
            #pragma unroll
            for (int r = 0; r < 4; r++) acc[i][j][r] = 0.f;

#define COMPUTE_HALF(half)                                                     \
    _Pragma("unroll")                                                          \
    for (int kss = 0; kss < 4; kss++) {                                        \
        int ks = (half) * 4 + kss;                                             \
        uint4 a[4];                                                            \
        uint2 bf[4];                                                           \
        _Pragma("unroll")                                                      \
        for (int i = 0; i < 4; i++)                                            \
            a[i] = *(const uint4*)&dyn[((wm * 4 + i) * 8 + ks) * 128 + lane * 4]; \
        _Pragma("unroll")                                                      \
        for (int j = 0; j < 4; j++) {                                          \
            float4 br = *(const float4*)&Braw[((wn * 4 + j) * 8 + ks) * 128 + lane * 4]; \
            bf[j].x = pack_h2(br.y, br.x);                                     \
            bf[j].y = pack_h2(br.w, br.z);                                     \
        }                                                                      \
        _Pragma("unroll")                                                      \
        for (int i = 0; i < 4; i++)                                            \
            _Pragma("unroll")                                                  \
            for (int j = 0; j < 4; j++)                                        \
                mma_f16(acc[i][j], a[i], bf[j]);                               \
    }

    CP_WAIT(1);
    __syncthreads();       // half0 B + A frags + c_s visible
    COMPUTE_HALF(0);
    CP_WAIT(0);
    __syncthreads();       // half1 B visible
    COMPUTE_HALF(1);

    // ---- epilogue: e[f] = b2 + sum_t W2[t] * tanh(D[t][f] + c[t]) ----
    float b2v = __ldg(&b2[0]);
    float es[4][2];
    #pragma unroll
    for (int j = 0; j < 4; j++) { es[j][0] = 0.f; es[j][1] = 0.f; }
    #pragma unroll
    for (int i = 0; i < 4; i++) {
        int t0 = (wm * 4 + i) * 16 + g;
        float c0 = c_s[t0],     w0 = w2_s[t0];
        float c1 = c_s[t0 + 8], w1 = w2_s[t0 + 8];
        #pragma unroll
        for (int j = 0; j < 4; j++) {
            es[j][0] += w0 * tanh_fast(acc[i][j][0] + c0)
                      + w1 * tanh_fast(acc[i][j][2] + c1);
            es[j][1] += w0 * tanh_fast(acc[i][j][1] + c0)
                      + w1 * tanh_fast(acc[i][j][3] + c1);
        }
    }
    #pragma unroll
    for (int j = 0; j < 4; j++)
        #pragma unroll
        for (int s2 = 0; s2 < 2; s2++) {
            float v = es[j][s2];
            v += __shfl_xor_sync(0xffffffffu, v, 4);
            v += __shfl_xor_sync(0xffffffffu, v, 8);
            v += __shfl_xor_sync(0xffffffffu, v, 16);
            es[j][s2] = v;
        }
    if (lane < 4) {
        #pragma unroll
        for (int j = 0; j < 4; j++) {
            int fl = (wn * 4 + j) * 8 + 2 * lane;
            red2[wm][fl]     = es[j][0];
            red2[wm][fl + 1] = es[j][1];
        }
    }
    __syncthreads();
    if (tid < 128)
        g_e[b * Fn + f0 + tid] = red2[0][tid] + red2[1][tid] + b2v;
}

// ---------------------------------------------------------------------------
// k3: softmax over f per batch
// ---------------------------------------------------------------------------
__global__ void k3_softmax(float* __restrict__ out) {
    __shared__ float smr[256];
    int b = blockIdx.x, tid = threadIdx.x;
    const float* eb = g_e + b * Fn;
    float v[4];
    float m = -1e30f;
    #pragma unroll
    for (int i = 0; i < 4; i++) { v[i] = eb[tid + i * 256]; m = fmaxf(m, v[i]); }
    smr[tid] = m; __syncthreads();
    for (int st = 128; st > 0; st >>= 1) {
        if (tid < st) smr[tid] = fmaxf(smr[tid], smr[tid + st]);
        __syncthreads();
    }
    m = smr[0];
    __syncthreads();
    float sum = 0.f;
    #pragma unroll
    for (int i = 0; i < 4; i++) { v[i] = __expf(v[i] - m); sum += v[i]; }
    smr[tid] = sum; __syncthreads();
    for (int st = 128; st > 0; st >>= 1) {
        if (tid < st) smr[tid] += smr[tid + st];
        __syncthreads();
    }
    float inv = 1.f / smr[0];
    #pragma unroll
    for (int i = 0; i < 4; i++) out[b * Fn + tid + i * 256] = v[i] * inv;
}

extern "C" void kernel_launch(void* const* d_in, const int* in_sizes, int n_in,
                              void* d_out, int out_size) {
    const float* h  = (const float*)d_in[0];
    const float* s  = (const float*)d_in[1];
    const float* x  = (const float*)d_in[2];
    const float* W1 = (const float*)d_in[3];
    const float* b1 = (const float*)d_in[4];
    const float* W2 = (const float*)d_in[5];
    const float* b2 = (const float*)d_in[6];
    float* out = (float*)d_out;

    static int init_done = 0;
    if (!init_done) {
        cudaFuncSetAttribute(k2_main, cudaFuncAttributeMaxDynamicSharedMemorySize,
                             98304);
        cudaFuncSetAttribute(k1_mma, cudaFuncAttributeMaxDynamicSharedMemorySize,
                             65536);
        init_done = 1;
    }

    dim3 g1(KSP, Bn / 128);
    k1_mma<<<g1, 256, 65536>>>(h, s, W1, b1);
    dim3 g2(Fn / 128, Bn);
    k2_main<<<g2, 256, 98304>>>(x, W1, W2, b2);
    k3_softmax<<<Bn, 256>>>(out);
}

// round 9
// speedup vs baseline: 1.4007x; 1.4007x over previous
#include <cuda_runtime.h>
#include <math.h>
#include <stdint.h>

#define Bn 256
#define Tn 128
#define Fn 1024
#define Hn 512
#define IN1 1152
#define KSP 16         // k1 K-splits (64-wide slices of the 1024 hs dim)

__device__ float g_cp[KSP][Bn * Tn];  // k1 partials (D[t,b] slices)
__device__ float g_e[Bn * Fn];        // logits

__device__ __forceinline__ float tanh_fast(float x) {
    float y; asm("tanh.approx.f32 %0, %1;" : "=f"(y) : "f"(x)); return y;
}
__device__ __forceinline__ uint32_t pack_h2(float hi, float lo) {
    uint32_t d;
    asm("cvt.rn.f16x2.f32 %0, %1, %2;" : "=r"(d) : "f"(hi), "f"(lo));
    return d;
}
__device__ __forceinline__ void mma_f16(float* d, const uint4& a, const uint2& b) {
    asm volatile(
        "mma.sync.aligned.m16n8k16.row.col.f32.f16.f16.f32 "
        "{%0,%1,%2,%3}, {%4,%5,%6,%7}, {%8,%9}, {%0,%1,%2,%3};"
        : "+f"(d[0]), "+f"(d[1]), "+f"(d[2]), "+f"(d[3])
        : "r"(a.x), "r"(a.y), "r"(a.z), "r"(a.w), "r"(b.x), "r"(b.y));
}

// ---------------------------------------------------------------------------
// k1: c partials via fp16 mma. grid (KSP=16, 4) = 64 CTAs.
// CTA: D[t=128, b=64] for one K=64 slice of hs.
// 8 warps = 2(M) x 4(N); warp tile 64t x 16b. 4 k-steps.
// Dynamic smem (u32): A frags [8 mt][4 ks][128] = 4096 | B frags [8 nt][4 ks][64] = 2048.
// ---------------------------------------------------------------------------
__global__ __launch_bounds__(256) void k1_mma(
    const float* __restrict__ h, const float* __restrict__ s,
    const float* __restrict__ W1, const float* __restrict__ b1) {
    extern __shared__ uint32_t dynA[];            // A at 0, B at 4096
    int tid = threadIdx.x;
    int w = tid >> 5, lane = tid & 31;
    int wm = w >> 2, wn = w & 3;
    int g = lane >> 2, tq = lane & 3;
    int ksl = blockIdx.x;          // K slice (0..15): j = ksl*64 + kk
    int b0  = blockIdx.y * 64;     // batch tile

    // ---- stage B first (h/s rows, k-contiguous): warp w -> nt = w ----
    {
        const float* base = (ksl < 8) ? h : s;
        int joff = (ksl & 7) * 64;
        const float* row = base + (size_t)(b0 + w * 8 + g) * Hn + joff;
        #pragma unroll
        for (int ks = 0; ks < 4; ks++) {
            int k0 = ks * 16 + 2 * tq;
            float2 p0 = *(const float2*)(row + k0);
            float2 p1 = *(const float2*)(row + k0 + 8);
            uint2 bv;
            bv.x = pack_h2(p0.y, p0.x);
            bv.y = pack_h2(p1.y, p1.x);
            *(uint2*)&dynA[4096 + (w * 4 + ks) * 64 + lane * 2] = bv;
        }
    }
    // ---- stage A: warp w -> mt = w (t rows w*16+g, +8) ----
    {
        const float* r0 = W1 + (size_t)(w * 16 + g) * IN1 + Tn + ksl * 64;
        const float* r8 = r0 + 8 * IN1;
        #pragma unroll
        for (int ks = 0; ks < 4; ks++) {
            int c0 = ks * 16 + 2 * tq;
            float2 p00 = *(const float2*)(r0 + c0);
            float2 p10 = *(const float2*)(r8 + c0);
            float2 p01 = *(const float2*)(r0 + c0 + 8);
            float2 p11 = *(const float2*)(r8 + c0 + 8);
            uint4 v;
            v.x = pack_h2(p00.y, p00.x);
            v.y = pack_h2(p10.y, p10.x);
            v.z = pack_h2(p01.y, p01.x);
            v.w = pack_h2(p11.y, p11.x);
            *(uint4*)&dynA[(w * 4 + ks) * 128 + lane * 4] = v;
        }
    }
    __syncthreads();

    float acc[4][2][4];
    #pragma unroll
    for (int i = 0; i < 4; i++)
        #pragma unroll
        for (int j = 0; j < 2; j++)
            #pragma unroll
            for (int r = 0; r < 4; r++) acc[i][j][r] = 0.f;

    #pragma unroll
    for (int ks = 0; ks < 4; ks++) {
        uint4 a[4];
        uint2 bf[2];
        #pragma unroll
        for (int i = 0; i < 4; i++)
            a[i] = *(const uint4*)&dynA[((wm * 4 + i) * 4 + ks) * 128 + lane * 4];
        #pragma unroll
        for (int j = 0; j < 2; j++)
            bf[j] = *(const uint2*)&dynA[4096 + ((wn * 2 + j) * 4 + ks) * 64 + lane * 2];
        #pragma unroll
        for (int i = 0; i < 4; i++)
            #pragma unroll
            for (int j = 0; j < 2; j++)
                mma_f16(acc[i][j], a[i], bf[j]);
    }

    // ---- store partials: D[t, b] -> g_cp[ksl][b*Tn + t]  (+ b1 on slice 0) ----
    #pragma unroll
    for (int i = 0; i < 4; i++) {
        int t0 = (wm * 4 + i) * 16 + g;
        float bias0 = (ksl == 0) ? __ldg(&b1[t0])     : 0.f;
        float bias1 = (ksl == 0) ? __ldg(&b1[t0 + 8]) : 0.f;
        #pragma unroll
        for (int j = 0; j < 2; j++) {
            int bc = b0 + (wn * 2 + j) * 8 + 2 * tq;
            g_cp[ksl][(bc)     * Tn + t0]     = acc[i][j][0] + bias0;
            g_cp[ksl][(bc + 1) * Tn + t0]     = acc[i][j][1] + bias0;
            g_cp[ksl][(bc)     * Tn + t0 + 8] = acc[i][j][2] + bias1;
            g_cp[ksl][(bc + 1) * Tn + t0 + 8] = acc[i][j][3] + bias1;
        }
    }
}

// ---------------------------------------------------------------------------
// k2: mma.sync fp16 m16n8k16, ALL of K=128 staged once (R7 champion).
// CTA = (f-tile 128, batch b). 8 warps = 2(M) x 4(N); warp tile 64t x 32f.
// B (cold, DRAM) staged before A (hot, L1/L2) to overlap latency.
// Dynamic smem (u32): A frags [8][8][128] = 8192 | B frags [16][8][64] = 8192.
// ---------------------------------------------------------------------------
__global__ __launch_bounds__(256, 2) void k2_main(
    const float* __restrict__ x, const float* __restrict__ W1,
    const float* __restrict__ W2, const float* __restrict__ b2) {
    extern __shared__ uint32_t dyn[];   // A at 0, B at 8192
    __shared__ float c_s[Tn], w2_s[Tn];
    __shared__ float red2[2][128];

    int tid = threadIdx.x;
    int w = tid >> 5, lane = tid & 31;
    int wm = w >> 2, wn = w & 3;
    int g = lane >> 2, tq = lane & 3;
    int b  = blockIdx.y;
    int f0 = blockIdx.x * 128;

    // ---- stage B first: warp w handles nt = 2w, 2w+1 (f cols nt*8..nt*8+7) ----
    {
        const float* xb = x + (size_t)b * Tn * Fn + f0;
        #pragma unroll
        for (int jj = 0; jj < 2; jj++) {
            int nt = w * 2 + jj;
            const float* col = xb + nt * 8 + g;
            #pragma unroll
            for (int ks = 0; ks < 8; ks++) {
                int k0 = ks * 16 + 2 * tq;
                float v00 = __ldg(col + (size_t)k0 * Fn);
                float v01 = __ldg(col + (size_t)(k0 + 1) * Fn);
                float v10 = __ldg(col + (size_t)(k0 + 8) * Fn);
                float v11 = __ldg(col + (size_t)(k0 + 9) * Fn);
                uint2 bv;
                bv.x = pack_h2(v01, v00);
                bv.y = pack_h2(v11, v10);
                *(uint2*)&dyn[8192 + (nt * 8 + ks) * 64 + lane * 2] = bv;
            }
        }
    }
    // ---- stage A: warp w handles mt = w (t rows w*16 .. w*16+15) ----
    {
        const float* r0 = W1 + (size_t)(w * 16 + g) * IN1;
        const float* r8 = r0 + 8 * IN1;
        #pragma unroll
        for (int ks = 0; ks < 8; ks++) {
            int c0 = ks * 16 + 2 * tq;
            float2 p00 = *(const float2*)(r0 + c0);
            float2 p10 = *(const float2*)(r8 + c0);
            float2 p01 = *(const float2*)(r0 + c0 + 8);
            float2 p11 = *(const float2*)(r8 + c0 + 8);
            uint4 v;
            v.x = pack_h2(p00.y, p00.x);
            v.y = pack_h2(p10.y, p10.x);
            v.z = pack_h2(p01.y, p01.x);
            v.w = pack_h2(p11.y, p11.x);
            *(uint4*)&dyn[(w * 8 + ks) * 128 + lane * 4] = v;
        }
    }

    if (tid < Tn) {
        float c = 0.f;
        #pragma unroll
        for (int k = 0; k < KSP; k++) c += g_cp[k][b * Tn + tid];
        c_s[tid]  = c;
        w2_s[tid] = __ldg(&W2[tid]);
    }
    __syncthreads();

    // ---- compute: 8 k-steps x 4x4 mma ----
    float acc[4][4][4];
    #pragma unroll
    for (int i = 0; i < 4; i++)
        #pragma unroll
        for (int j = 0; j < 4; j++)
            #pragma unroll
            for (int r = 0; r < 4; r++) acc[i][j][r] = 0.f;

    #pragma unroll
    for (int ks = 0; ks < 8; ks++) {
        uint4 a[4];
        uint2 bf[4];
        #pragma unroll
        for (int i = 0; i < 4; i++)
            a[i] = *(const uint4*)&dyn[((wm * 4 + i) * 8 + ks) * 128 + lane * 4];
        #pragma unroll
        for (int j = 0; j < 4; j++)
            bf[j] = *(const uint2*)&dyn[8192 + ((wn * 4 + j) * 8 + ks) * 64 + lane * 2];
        #pragma unroll
        for (int i = 0; i < 4; i++)
            #pragma unroll
            for (int j = 0; j < 4; j++)
                mma_f16(acc[i][j], a[i], bf[j]);
    }

    // ---- epilogue: e[f] = b2 + sum_t W2[t] * tanh(D[t][f] + c[t]) ----
    float b2v = __ldg(&b2[0]);
    float es[4][2];
    #pragma unroll
    for (int j = 0; j < 4; j++) { es[j][0] = 0.f; es[j][1] = 0.f; }
    #pragma unroll
    for (int i = 0; i < 4; i++) {
        int t0 = (wm * 4 + i) * 16 + g;
        float c0 = c_s[t0],     w0 = w2_s[t0];
        float c1 = c_s[t0 + 8], w1 = w2_s[t0 + 8];
        #pragma unroll
        for (int j = 0; j < 4; j++) {
            es[j][0] += w0 * tanh_fast(acc[i][j][0] + c0)
                      + w1 * tanh_fast(acc[i][j][2] + c1);
            es[j][1] += w0 * tanh_fast(acc[i][j][1] + c0)
                      + w1 * tanh_fast(acc[i][j][3] + c1);
        }
    }
    #pragma unroll
    for (int j = 0; j < 4; j++)
        #pragma unroll
        for (int s2 = 0; s2 < 2; s2++) {
            float v = es[j][s2];
            v += __shfl_xor_sync(0xffffffffu, v, 4);
            v += __shfl_xor_sync(0xffffffffu, v, 8);
            v += __shfl_xor_sync(0xffffffffu, v, 16);
            es[j][s2] = v;
        }
    if (lane < 4) {
        #pragma unroll
        for (int j = 0; j < 4; j++) {
            int fl = (wn * 4 + j) * 8 + 2 * lane;
            red2[wm][fl]     = es[j][0];
            red2[wm][fl + 1] = es[j][1];
        }
    }
    __syncthreads();
    if (tid < 128)
        g_e[b * Fn + f0 + tid] = red2[0][tid] + red2[1][tid] + b2v;
}

// ---------------------------------------------------------------------------
// k3: softmax over f per batch
// ---------------------------------------------------------------------------
__global__ void k3_softmax(float* __restrict__ out) {
    __shared__ float smr[256];
    int b = blockIdx.x, tid = threadIdx.x;
    const float* eb = g_e + b * Fn;
    float v[4];
    float m = -1e30f;
    #pragma unroll
    for (int i = 0; i < 4; i++) { v[i] = eb[tid + i * 256]; m = fmaxf(m, v[i]); }
    smr[tid] = m; __syncthreads();
    for (int st = 128; st > 0; st >>= 1) {
        if (tid < st) smr[tid] = fmaxf(smr[tid], smr[tid + st]);
        __syncthreads();
    }
    m = smr[0];
    __syncthreads();
    float sum = 0.f;
    #pragma unroll
    for (int i = 0; i < 4; i++) { v[i] = __expf(v[i] - m); sum += v[i]; }
    smr[tid] = sum; __syncthreads();
    for (int st = 128; st > 0; st >>= 1) {
        if (tid < st) smr[tid] += smr[tid + st];
        __syncthreads();
    }
    float inv = 1.f / smr[0];
    #pragma unroll
    for (int i = 0; i < 4; i++) out[b * Fn + tid + i * 256] = v[i] * inv;
}

extern "C" void kernel_launch(void* const* d_in, const int* in_sizes, int n_in,
                              void* d_out, int out_size) {
    const float* h  = (const float*)d_in[0];
    const float* s  = (const float*)d_in[1];
    const float* x  = (const float*)d_in[2];
    const float* W1 = (const float*)d_in[3];
    const float* b1 = (const float*)d_in[4];
    const float* W2 = (const float*)d_in[5];
    const float* b2 = (const float*)d_in[6];
    float* out = (float*)d_out;

    static int init_done = 0;
    if (!init_done) {
        cudaFuncSetAttribute(k2_main, cudaFuncAttributeMaxDynamicSharedMemorySize,
                             65536);
        cudaFuncSetAttribute(k1_mma, cudaFuncAttributeMaxDynamicSharedMemorySize,
                             24576);
        init_done = 1;
    }

    dim3 g1(KSP, Bn / 64);
    k1_mma<<<g1, 256, 24576>>>(h, s, W1, b1);
    dim3 g2(Fn / 128, Bn);
    k2_main<<<g2, 256, 65536>>>(x, W1, W2, b2);
    k3_softmax<<<Bn, 256>>>(out);
}